// round 10
// baseline (speedup 1.0000x reference)
#include <cuda_runtime.h>
#include <cuda_bf16.h>
#include <stdint.h>

#define N_FINE_MAX 200000

// Scratch: inverse map  g_map[unpool_nodes[i]] = i.
// Only entries at positions in unpool_nodes are ever read.
__device__ int g_map[N_FINE_MAX];

__global__ void build_map_kernel(const int* __restrict__ nodes, int n_coarse) {
    int i = blockIdx.x * blockDim.x + threadIdx.x;
    if (i < n_coarse) g_map[nodes[i]] = i;
}

// 32-byte load (two float4) with L2 evict_last: sm_103 ptxas only allows the
// evict_last modifier on .v8.b32/.v4.b64 shapes. x (102MB) nearly fits L2
// (126MB) and has ~4x reuse; protect it from the streaming output stores.
__device__ __forceinline__ void ldg_el_32B(const float4* p, float4& a, float4& b) {
    unsigned long long r0, r1, r2, r3;
    asm("ld.global.nc.L2::evict_last.v4.b64 {%0,%1,%2,%3}, [%4];"
        : "=l"(r0), "=l"(r1), "=l"(r2), "=l"(r3) : "l"(p));
    a.x = __uint_as_float((unsigned)r0); a.y = __uint_as_float((unsigned)(r0 >> 32));
    a.z = __uint_as_float((unsigned)r1); a.w = __uint_as_float((unsigned)(r1 >> 32));
    b.x = __uint_as_float((unsigned)r2); b.y = __uint_as_float((unsigned)(r2 >> 32));
    b.z = __uint_as_float((unsigned)r3); b.w = __uint_as_float((unsigned)(r3 >> 32));
}

// Streaming (evict-first) store for the 410MB output: never reused, must not
// displace the x working set in L2.
__device__ __forceinline__ void stg_cs(float4* p, float4 v) {
    asm volatile("st.global.cs.v4.f32 [%0], {%1,%2,%3,%4};"
                 :: "l"(p), "f"(v.x), "f"(v.y), "f"(v.z), "f"(v.w) : "memory");
}

// One warp per edge. Each edge moves 512 floats = 128 float4.
// Each lane owns two consecutive float4 (32B) per half:
//   part 0: float4 indices 2*lane, 2*lane+1         (straight copy)
//   part 1: float4 indices 64+2*lane, 64+2*lane+1   (rotate by conj(connection))
__global__ __launch_bounds__(256) void unpool_kernel(
    const float4* __restrict__ x,        // (N_COARSE * 128) float4  [c,part,k,comp]
    const float2* __restrict__ conn,     // (N_FINE) float2 (cos, sin)
    const int*    __restrict__ edge_src, // (N_FINE)
    const int*    __restrict__ edge_dst, // (N_FINE)
    float4*       __restrict__ out,      // (N_FINE * 128) float4
    int n_fine)
{
    int warp = (int)((blockIdx.x * blockDim.x + threadIdx.x) >> 5);
    int lane = threadIdx.x & 31;
    if (warp >= n_fine) return;

    const int e = warp;
    const int s = __ldg(&edge_src[e]);
    const int d = __ldg(&edge_dst[e]);
    const int c = g_map[s];                 // L2 gather (800 KB table)
    const float2 cs = __ldg(&conn[e]);      // warp-uniform address -> 1 transaction

    const float4* __restrict__ src = x   + (size_t)c * 128;
    float4*       __restrict__ dst = out + (size_t)d * 128;

    // Part 0: x[c,0,:,:] -> out[d,0,:,:]  (straight copy)
    {
        float4 v0, v1;
        ldg_el_32B(&src[2 * lane], v0, v1);
        stg_cs(&dst[2 * lane],     v0);
        stg_cs(&dst[2 * lane + 1], v1);
    }

    // Part 1: rotate by conj(connection): b = (cos, -sin)
    //   out_re = a_re*cos + a_im*sin
    //   out_im = a_im*cos - a_re*sin
    const float co = cs.x;
    const float si = cs.y;
    {
        float4 v0, v1;
        ldg_el_32B(&src[64 + 2 * lane], v0, v1);
        float4 r0, r1;
        r0.x = fmaf(v0.x, co,  v0.y * si);
        r0.y = fmaf(v0.y, co, -v0.x * si);
        r0.z = fmaf(v0.z, co,  v0.w * si);
        r0.w = fmaf(v0.w, co, -v0.z * si);
        r1.x = fmaf(v1.x, co,  v1.y * si);
        r1.y = fmaf(v1.y, co, -v1.x * si);
        r1.z = fmaf(v1.z, co,  v1.w * si);
        r1.w = fmaf(v1.w, co, -v1.z * si);
        stg_cs(&dst[64 + 2 * lane],     r0);
        stg_cs(&dst[64 + 2 * lane + 1], r1);
    }
}

extern "C" void kernel_launch(void* const* d_in, const int* in_sizes, int n_in,
                              void* d_out, int out_size) {
    // metadata order: x, unpool_connection, unpool_nodes, unpool_edges, num_nodes
    const float* x      = (const float*)d_in[0];
    const float* conn   = (const float*)d_in[1];
    const int*   nodes  = (const int*)d_in[2];
    const int*   edges  = (const int*)d_in[3];

    const int n_coarse = in_sizes[0] / 512;   // x: (n_coarse, 2, 128, 2)
    const int n_fine   = in_sizes[3] / 2;     // edges: (2, n_fine)

    const int* edge_src = edges;
    const int* edge_dst = edges + n_fine;

    // 1) Build inverse unpool map (scatter, ~50K threads)
    {
        int threads = 256;
        int blocks  = (n_coarse + threads - 1) / threads;
        build_map_kernel<<<blocks, threads>>>(nodes, n_coarse);
    }

    // 2) One warp per edge: gather + rotate + scatter
    {
        int threads = 256;                       // 8 warps/block
        int warps_per_block = threads / 32;
        int blocks = (n_fine + warps_per_block - 1) / warps_per_block;
        unpool_kernel<<<blocks, threads>>>(
            (const float4*)x, (const float2*)conn,
            edge_src, edge_dst, (float4*)d_out, n_fine);
    }
}

// round 13
// speedup vs baseline: 1.8697x; 1.8697x over previous
#include <cuda_runtime.h>
#include <cuda_bf16.h>
#include <stdint.h>

#define N_COARSE_MAX 50000
#define N_FINE_MAX   200000
#define BIN_CAP      32   // Poisson(mean=4) max bin count; P(>=32) ~ 1e-22

// Scratch (static device arrays; no allocation in kernel_launch).
__device__ int g_map[N_FINE_MAX];              // fine node id -> coarse index
__device__ int g_cnt[N_COARSE_MAX];            // edges per coarse node
__device__ int g_bin[N_COARSE_MAX * BIN_CAP];  // edge ids grouped by coarse node

// K1: build inverse map and zero bin counters.
__global__ void build_map_kernel(const int* __restrict__ nodes, int n_coarse) {
    int i = blockIdx.x * blockDim.x + threadIdx.x;
    if (i < n_coarse) {
        g_map[nodes[i]] = i;
        g_cnt[i] = 0;
    }
}

// K2: bin edges by their coarse source index.
__global__ void bin_edges_kernel(const int* __restrict__ edge_src, int n_fine) {
    int e = blockIdx.x * blockDim.x + threadIdx.x;
    if (e >= n_fine) return;
    int c = g_map[edge_src[e]];
    int slot = atomicAdd(&g_cnt[c], 1);
    if (slot < BIN_CAP) g_bin[c * BIN_CAP + slot] = e;
}

// K3: one warp per coarse node. Load the 2KB x-row ONCE into registers, then
// write it to every destination in this node's edge list (part0 copied,
// part1 rotated by conj(connection) per edge).
//
// Row layout: 128 float4 = [part(2) x k(128) x comp(2)] floats.
//   lane owns float4 indices lane+32*j, j=0..3. j=0,1 -> part0; j=2,3 -> part1.
__global__ __launch_bounds__(256) void unpool_kernel(
    const float4* __restrict__ x,        // (n_coarse * 128) float4
    const float2* __restrict__ conn,     // (n_fine) float2 (cos, sin)
    const int*    __restrict__ edge_dst, // (n_fine)
    float4*       __restrict__ out,      // (n_fine * 128) float4
    int n_coarse)
{
    int warp = (int)((blockIdx.x * blockDim.x + threadIdx.x) >> 5);
    int lane = threadIdx.x & 31;
    if (warp >= n_coarse) return;

    const int c = warp;
    int cnt = g_cnt[c];                  // warp-uniform
    if (cnt > BIN_CAP) cnt = BIN_CAP;    // defensive clamp
    if (cnt == 0) return;

    // Per-lane metadata for edge i = lane (cnt <= 32 guaranteed).
    int my_d = 0;
    float my_co = 0.f, my_si = 0.f;
    if (lane < cnt) {
        int my_e = g_bin[c * BIN_CAP + lane];
        my_d = __ldg(&edge_dst[my_e]);
        float2 cs = __ldg(&conn[my_e]);
        my_co = cs.x;
        my_si = cs.y;
    }

    // Load the source row once: sequential streaming (row c == warp id).
    const float4* __restrict__ src = x + (size_t)c * 128;
    float4 v0 = __ldg(&src[lane]);
    float4 v1 = __ldg(&src[lane + 32]);
    float4 v2 = __ldg(&src[lane + 64]);
    float4 v3 = __ldg(&src[lane + 96]);

    // Emit one output row per edge.
    for (int i = 0; i < cnt; ++i) {
        int   d  = __shfl_sync(0xffffffffu, my_d,  i);
        float co = __shfl_sync(0xffffffffu, my_co, i);
        float si = __shfl_sync(0xffffffffu, my_si, i);

        float4* __restrict__ dst = out + (size_t)d * 128;

        // part 0: straight copy
        dst[lane]      = v0;
        dst[lane + 32] = v1;

        // part 1: multiply by conj(connection): b = (cos, -sin)
        //   out_re = a_re*cos + a_im*sin ;  out_im = a_im*cos - a_re*sin
        float4 r2, r3;
        r2.x = fmaf(v2.x, co,  v2.y * si);
        r2.y = fmaf(v2.y, co, -v2.x * si);
        r2.z = fmaf(v2.z, co,  v2.w * si);
        r2.w = fmaf(v2.w, co, -v2.z * si);
        r3.x = fmaf(v3.x, co,  v3.y * si);
        r3.y = fmaf(v3.y, co, -v3.x * si);
        r3.z = fmaf(v3.z, co,  v3.w * si);
        r3.w = fmaf(v3.w, co, -v3.z * si);
        dst[lane + 64] = r2;
        dst[lane + 96] = r3;
    }
}

extern "C" void kernel_launch(void* const* d_in, const int* in_sizes, int n_in,
                              void* d_out, int out_size) {
    // metadata order: x, unpool_connection, unpool_nodes, unpool_edges, num_nodes
    const float* x      = (const float*)d_in[0];
    const float* conn   = (const float*)d_in[1];
    const int*   nodes  = (const int*)d_in[2];
    const int*   edges  = (const int*)d_in[3];

    const int n_coarse = in_sizes[0] / 512;   // x: (n_coarse, 2, 128, 2)
    const int n_fine   = in_sizes[3] / 2;     // edges: (2, n_fine)

    const int* edge_src = edges;
    const int* edge_dst = edges + n_fine;

    // K1: inverse map + zero counters
    {
        int threads = 256;
        int blocks  = (n_coarse + threads - 1) / threads;
        build_map_kernel<<<blocks, threads>>>(nodes, n_coarse);
    }
    // K2: bin edges by coarse source
    {
        int threads = 256;
        int blocks  = (n_fine + threads - 1) / threads;
        bin_edges_kernel<<<blocks, threads>>>(edge_src, n_fine);
    }
    // K3: one warp per coarse node; row loaded once, fanned out to all dsts
    {
        int threads = 256;                       // 8 warps/block
        int warps_per_block = threads / 32;
        int blocks = (n_coarse + warps_per_block - 1) / warps_per_block;
        unpool_kernel<<<blocks, threads>>>(
            (const float4*)x, (const float2*)conn,
            edge_dst, (float4*)d_out, n_coarse);
    }
}